// round 4
// baseline (speedup 1.0000x reference)
#include <cuda_runtime.h>
#include <cuda_fp16.h>
#include <cstdint>

#define MMV 2048
#define NNV 4096
#define KKV 4096

// Scratch (__device__ globals; no allocations allowed)
__device__ __align__(16) __half g_xh[(size_t)MMV * KKV];  // fp16(x)
__device__ __align__(16) __half g_wi[(size_t)KKV * NNV];  // (q - z) exact integer, [K][N]

// ---------------------------------------------------------------------------
// asm helpers (plain-sm_103-legal: ldmatrix / mma.sync / cp.async)
// ---------------------------------------------------------------------------
__device__ __forceinline__ void ldsm4(uint32_t* r, uint32_t addr) {
    asm volatile("ldmatrix.sync.aligned.m8n8.x4.shared.b16 {%0,%1,%2,%3}, [%4];"
                 : "=r"(r[0]), "=r"(r[1]), "=r"(r[2]), "=r"(r[3]) : "r"(addr));
}
__device__ __forceinline__ void ldsm4t(uint32_t* r, uint32_t addr) {
    asm volatile("ldmatrix.sync.aligned.m8n8.x4.trans.shared.b16 {%0,%1,%2,%3}, [%4];"
                 : "=r"(r[0]), "=r"(r[1]), "=r"(r[2]), "=r"(r[3]) : "r"(addr));
}
__device__ __forceinline__ void mma_f16(float* c, const uint32_t* a, const uint32_t* b) {
    asm volatile("mma.sync.aligned.m16n8k16.row.col.f32.f16.f16.f32 "
                 "{%0,%1,%2,%3}, {%4,%5,%6,%7}, {%8,%9}, {%0,%1,%2,%3};"
                 : "+f"(c[0]), "+f"(c[1]), "+f"(c[2]), "+f"(c[3])
                 : "r"(a[0]), "r"(a[1]), "r"(a[2]), "r"(a[3]), "r"(b[0]), "r"(b[1]));
}
__device__ __forceinline__ void cpa16(uint32_t s, const void* g) {
    asm volatile("cp.async.cg.shared.global [%0], [%1], 16;" :: "r"(s), "l"(g));
}
#define CP_COMMIT() asm volatile("cp.async.commit_group;" ::: "memory")
#define CP_WAIT5()  asm volatile("cp.async.wait_group 5;" ::: "memory")

// ---------------------------------------------------------------------------
// Prep 1: x -> fp16
// ---------------------------------------------------------------------------
__global__ void split_x_kernel(const float4* __restrict__ x4) {
    size_t i = (size_t)blockIdx.x * blockDim.x + threadIdx.x;  // M*K/4 threads
    float4 v = x4[i];
    float f[4] = {v.x, v.y, v.z, v.w};
    __align__(8) __half h[4];
#pragma unroll
    for (int j = 0; j < 4; ++j) h[j] = __float2half_rn(f[j]);
    ((uint2*)g_xh)[i] = *(uint2*)h;
}

// ---------------------------------------------------------------------------
// Prep 2: Wint[k][n] = q - clip(round(zp),0,15)  (exact small integer, fp16)
// ---------------------------------------------------------------------------
__global__ void dequant_w_kernel(const int* __restrict__ qw,
                                 const float* __restrict__ zp) {
    int T = blockIdx.x * blockDim.x + threadIdx.x;  // KKV/8 * NNV threads
    int n  = T & (NNV - 1);
    int kp = T >> 12;
    int g  = kp >> 4;           // GROUP=128 -> 16 packed rows per group
    float z = fminf(fmaxf(rintf(zp[g * NNV + n]), 0.0f), 15.0f);
    int q = qw[(size_t)kp * NNV + n];
#pragma unroll
    for (int j = 0; j < 8; ++j) {
        int w = (q >> (4 * j)) & 15;
        g_wi[(size_t)(kp * 8 + j) * NNV + n] = __float2half_rn((float)w - z);
    }
}

// ---------------------------------------------------------------------------
// GEMM: C = xh @ Wint  with per-group fp32 scale fold, + bias
// CTA tile 128x128, BK=32, 8 warps (4m x 2n), warp tile 32x64
// smem: [0,16K) clipped scales; 6 stages x (A 8K | B 8K)
// ---------------------------------------------------------------------------
#define NS 6
#define STG_BYTES 16384
#define SM_STAGES 16384
#define SMEM_TOTAL (SM_STAGES + NS * STG_BYTES)   // 114688

__global__ void __launch_bounds__(256, 1)
gemm_kernel(const float* __restrict__ scales,
            const float* __restrict__ bias,
            float* __restrict__ C)
{
    extern __shared__ __align__(16) char smem[];
    const uint32_t sb = (uint32_t)__cvta_generic_to_shared(smem);
    const int tid = threadIdx.x, lane = tid & 31, wid = tid >> 5;
    const int wm = wid & 3, wn = wid >> 2;
    const int m0 = blockIdx.y * 128, n0 = blockIdx.x * 128;

    // stage clipped scales [32 groups][128 cols]
    float* s_sc = (float*)smem;
    for (int i = tid; i < 4096; i += 256) {
        int g = i >> 7, j = i & 127;
        float s = scales[g * NNV + n0 + j];
        s_sc[i] = fminf(fmaxf(s, 1e-5f), 1e4f);
    }

    // loader: A 128x32 fp16 (512 x 16B chunks), B 32x128 fp16 (512 chunks)
    auto load_stage = [&](int kt, int st) {
        uint32_t base = sb + SM_STAGES + st * STG_BYTES;
#pragma unroll
        for (int j = 0; j < 2; ++j) {
            int q = tid + j * 256;
            int r = q >> 2, c = q & 3;
            uint32_t so = base + (uint32_t)(r * 4 + (c ^ ((r >> 1) & 3))) * 16;
            cpa16(so, g_xh + (size_t)(m0 + r) * KKV + kt * 32 + c * 8);
        }
#pragma unroll
        for (int j = 0; j < 2; ++j) {
            int q = tid + j * 256;
            int r = q >> 4, c = q & 15;
            uint32_t so = base + 8192 + (uint32_t)(r * 16 + (c ^ (r & 7))) * 16;
            cpa16(so, g_wi + (size_t)(kt * 32 + r) * NNV + n0 + c * 8);
        }
    };

    // fill all 6 stages
#pragma unroll
    for (int s = 0; s < NS; ++s) { load_stage(s, s); CP_COMMIT(); }

    // ldmatrix address precompute
    const int lane_r = lane & 15, chh = lane >> 4;
    uint32_t aoff[2]; uint32_t axr[2];
#pragma unroll
    for (int t = 0; t < 2; ++t) {
        int r = wm * 32 + t * 16 + lane_r;
        aoff[t] = (uint32_t)r * 64;
        axr[t]  = (uint32_t)((r >> 1) & 3);
    }
    const uint32_t xb = (uint32_t)(lane_r & 7);
    uint32_t bcol[4];
#pragma unroll
    for (int bb = 0; bb < 4; ++bb)
        bcol[bb] = (uint32_t)(wn * 8 + (((uint32_t)(bb * 2 + chh)) ^ xb)) * 16;
    const uint32_t boff[2] = {(uint32_t)lane_r * 256, (uint32_t)(16 + lane_r) * 256};

    float accG[2][8][4];
    float accM[2][8][4];
#pragma unroll
    for (int t = 0; t < 2; ++t)
#pragma unroll
        for (int nt = 0; nt < 8; ++nt)
#pragma unroll
            for (int i = 0; i < 4; ++i) { accG[t][nt][i] = 0.f; accM[t][nt][i] = 0.f; }

    for (int kt = 0; kt < 128; ++kt) {
        CP_WAIT5();
        __syncthreads();

        const int st = kt % NS;
        const uint32_t Ab = sb + SM_STAGES + st * STG_BYTES;
        const uint32_t Bb = Ab + 8192;

#pragma unroll
        for (int ks = 0; ks < 2; ++ks) {
            uint32_t af[2][4], bfr[4][4];
#pragma unroll
            for (int t = 0; t < 2; ++t) {
                uint32_t co = ((uint32_t)(ks * 2 + chh) ^ axr[t]) * 16;
                ldsm4(af[t], Ab + aoff[t] + co);
            }
#pragma unroll
            for (int bb = 0; bb < 4; ++bb)
                ldsm4t(bfr[bb], Bb + boff[ks] + bcol[bb]);
#pragma unroll
            for (int t = 0; t < 2; ++t)
#pragma unroll
                for (int nt = 0; nt < 8; ++nt)
                    mma_f16(accG[t][nt], af[t], &bfr[nt >> 1][(nt & 1) * 2]);
        }

        if ((kt & 3) == 3) {   // end of 128-K group: fold with scales
            const int g = kt >> 2;
            const float* sg = s_sc + g * 128 + wn * 64 + (lane & 3) * 2;
#pragma unroll
            for (int nt = 0; nt < 8; ++nt) {
                float2 sv = *(const float2*)(sg + nt * 8);
#pragma unroll
                for (int t = 0; t < 2; ++t) {
                    accM[t][nt][0] += sv.x * accG[t][nt][0];
                    accM[t][nt][1] += sv.y * accG[t][nt][1];
                    accM[t][nt][2] += sv.x * accG[t][nt][2];
                    accM[t][nt][3] += sv.y * accG[t][nt][3];
                    accG[t][nt][0] = 0.f; accG[t][nt][1] = 0.f;
                    accG[t][nt][2] = 0.f; accG[t][nt][3] = 0.f;
                }
            }
        }

        __syncthreads();
        if (kt + NS < 128) load_stage(kt + NS, st);
        CP_COMMIT();
    }

    // epilogue
#pragma unroll
    for (int t = 0; t < 2; ++t) {
        int row0 = m0 + wm * 32 + t * 16 + (lane >> 2);
#pragma unroll
        for (int nt = 0; nt < 8; ++nt) {
            int col = n0 + wn * 64 + nt * 8 + (lane & 3) * 2;
            float2 b = *(const float2*)(bias + col);
            float2 o0, o1;
            o0.x = accM[t][nt][0] + b.x;  o0.y = accM[t][nt][1] + b.y;
            o1.x = accM[t][nt][2] + b.x;  o1.y = accM[t][nt][3] + b.y;
            *(float2*)(C + (size_t)row0 * NNV + col)       = o0;
            *(float2*)(C + (size_t)(row0 + 8) * NNV + col) = o1;
        }
    }
}

// ---------------------------------------------------------------------------
// Host. Inputs: x, scales, zero_points, bias, qweight
// ---------------------------------------------------------------------------
extern "C" void kernel_launch(void* const* d_in, const int* in_sizes, int n_in,
                              void* d_out, int out_size)
{
    const float* x      = (const float*)d_in[0];
    const float* scales = (const float*)d_in[1];
    const float* zp     = (const float*)d_in[2];
    const float* bias   = (const float*)d_in[3];
    const int*   qw     = (const int*)d_in[4];
    float*       out    = (float*)d_out;

    split_x_kernel<<<(MMV * KKV / 4) / 256, 256>>>((const float4*)x);
    dequant_w_kernel<<<(KKV / 8) * NNV / 256, 256>>>(qw, zp);

    static bool attr_set = false;
    if (!attr_set) {
        cudaFuncSetAttribute(gemm_kernel, cudaFuncAttributeMaxDynamicSharedMemorySize, SMEM_TOTAL);
        attr_set = true;
    }
    gemm_kernel<<<dim3(NNV / 128, MMV / 128), 256, SMEM_TOTAL>>>(scales, bias, out);
}

// round 5
// speedup vs baseline: 1.5147x; 1.5147x over previous
#include <cuda_runtime.h>
#include <cuda_fp16.h>
#include <cstdint>

#define MMV 2048
#define NNV 4096
#define KKV 4096

// Scratch (__device__ globals; no allocations allowed)
__device__ __align__(16) __half g_xh[(size_t)MMV * KKV];  // fp16(x)
__device__ __align__(16) __half g_wi[(size_t)KKV * NNV];  // (q - z) exact integer, [K][N]

// ---------------------------------------------------------------------------
// asm helpers (plain-sm_103-legal: ldmatrix / mma.sync / cp.async)
// ---------------------------------------------------------------------------
__device__ __forceinline__ void ldsm4(uint32_t* r, uint32_t addr) {
    asm volatile("ldmatrix.sync.aligned.m8n8.x4.shared.b16 {%0,%1,%2,%3}, [%4];"
                 : "=r"(r[0]), "=r"(r[1]), "=r"(r[2]), "=r"(r[3]) : "r"(addr));
}
__device__ __forceinline__ void ldsm4t(uint32_t* r, uint32_t addr) {
    asm volatile("ldmatrix.sync.aligned.m8n8.x4.trans.shared.b16 {%0,%1,%2,%3}, [%4];"
                 : "=r"(r[0]), "=r"(r[1]), "=r"(r[2]), "=r"(r[3]) : "r"(addr));
}
__device__ __forceinline__ void mma_f16(float* c, const uint32_t* a, const uint32_t* b) {
    asm volatile("mma.sync.aligned.m16n8k16.row.col.f32.f16.f16.f32 "
                 "{%0,%1,%2,%3}, {%4,%5,%6,%7}, {%8,%9}, {%0,%1,%2,%3};"
                 : "+f"(c[0]), "+f"(c[1]), "+f"(c[2]), "+f"(c[3])
                 : "r"(a[0]), "r"(a[1]), "r"(a[2]), "r"(a[3]), "r"(b[0]), "r"(b[1]));
}
__device__ __forceinline__ void cpa16(uint32_t s, const void* g) {
    asm volatile("cp.async.cg.shared.global [%0], [%1], 16;" :: "r"(s), "l"(g));
}
#define CP_COMMIT() asm volatile("cp.async.commit_group;" ::: "memory")
#define CP_WAIT5()  asm volatile("cp.async.wait_group 5;" ::: "memory")

// ---------------------------------------------------------------------------
// Prep 1: x -> fp16
// ---------------------------------------------------------------------------
__global__ void split_x_kernel(const float4* __restrict__ x4) {
    size_t i = (size_t)blockIdx.x * blockDim.x + threadIdx.x;  // M*K/4 threads
    float4 v = x4[i];
    float f[4] = {v.x, v.y, v.z, v.w};
    __align__(8) __half h[4];
#pragma unroll
    for (int j = 0; j < 4; ++j) h[j] = __float2half_rn(f[j]);
    ((uint2*)g_xh)[i] = *(uint2*)h;
}

// ---------------------------------------------------------------------------
// Prep 2: Wint[k][n] = q - clip(round(zp),0,15)  (exact small integer, fp16)
// ---------------------------------------------------------------------------
__global__ void dequant_w_kernel(const int* __restrict__ qw,
                                 const float* __restrict__ zp) {
    int T = blockIdx.x * blockDim.x + threadIdx.x;  // KKV/8 * NNV threads
    int n  = T & (NNV - 1);
    int kp = T >> 12;
    int g  = kp >> 4;           // GROUP=128 -> 16 packed rows per group
    float z = fminf(fmaxf(rintf(zp[g * NNV + n]), 0.0f), 15.0f);
    int q = qw[(size_t)kp * NNV + n];
#pragma unroll
    for (int j = 0; j < 8; ++j) {
        int w = (q >> (4 * j)) & 15;
        g_wi[(size_t)(kp * 8 + j) * NNV + n] = __float2half_rn((float)w - z);
    }
}

// ---------------------------------------------------------------------------
// GEMM: C = xh @ Wint  with per-group fp32 scale fold, + bias
// CTA tile 128x128, BK=32, 8 warps (4m x 2n), warp tile 32x64
// smem: [0,16K) clipped scales; 6 stages x (A 8K | B 8K)
// ---------------------------------------------------------------------------
#define NS 6
#define STG_BYTES 16384
#define SM_STAGES 16384
#define SMEM_TOTAL (SM_STAGES + NS * STG_BYTES)   // 114688

__global__ void __launch_bounds__(256, 1)
gemm_kernel(const float* __restrict__ scales,
            const float* __restrict__ bias,
            float* __restrict__ C)
{
    extern __shared__ __align__(16) char smem[];
    const uint32_t sb = (uint32_t)__cvta_generic_to_shared(smem);
    const int tid = threadIdx.x, lane = tid & 31, wid = tid >> 5;
    const int wm = wid & 3, wn = wid >> 2;
    const int m0 = blockIdx.y * 128, n0 = blockIdx.x * 128;

    // stage clipped scales [32 groups][128 cols]
    float* s_sc = (float*)smem;
    for (int i = tid; i < 4096; i += 256) {
        int g = i >> 7, j = i & 127;
        float s = scales[g * NNV + n0 + j];
        s_sc[i] = fminf(fmaxf(s, 1e-5f), 1e4f);
    }

    // loader: A 128x32 fp16 (512 x 16B chunks), B 32x128 fp16 (512 chunks)
    auto load_stage = [&](int kt, int st) {
        uint32_t base = sb + SM_STAGES + st * STG_BYTES;
#pragma unroll
        for (int j = 0; j < 2; ++j) {
            int q = tid + j * 256;
            int r = q >> 2, c = q & 3;
            uint32_t so = base + (uint32_t)(r * 4 + (c ^ ((r >> 1) & 3))) * 16;
            cpa16(so, g_xh + (size_t)(m0 + r) * KKV + kt * 32 + c * 8);
        }
#pragma unroll
        for (int j = 0; j < 2; ++j) {
            int q = tid + j * 256;
            int r = q >> 4, c = q & 15;
            uint32_t so = base + 8192 + (uint32_t)(r * 16 + (c ^ (r & 7))) * 16;
            cpa16(so, g_wi + (size_t)(kt * 32 + r) * NNV + n0 + c * 8);
        }
    };

    // fill all 6 stages
#pragma unroll
    for (int s = 0; s < NS; ++s) { load_stage(s, s); CP_COMMIT(); }

    // ldmatrix address precompute
    const int lane_r = lane & 15, chh = lane >> 4;
    uint32_t aoff[2]; uint32_t axr[2];
#pragma unroll
    for (int t = 0; t < 2; ++t) {
        int r = wm * 32 + t * 16 + lane_r;
        aoff[t] = (uint32_t)r * 64;
        axr[t]  = (uint32_t)((r >> 1) & 3);
    }
    const uint32_t xb = (uint32_t)(lane_r & 7);
    uint32_t bcol[4];
#pragma unroll
    for (int bb = 0; bb < 4; ++bb)
        bcol[bb] = (uint32_t)(wn * 8 + (((uint32_t)(bb * 2 + chh)) ^ xb)) * 16;
    const uint32_t boff[2] = {(uint32_t)lane_r * 256, (uint32_t)(16 + lane_r) * 256};

    float accG[2][8][4];
    float accM[2][8][4];
#pragma unroll
    for (int t = 0; t < 2; ++t)
#pragma unroll
        for (int nt = 0; nt < 8; ++nt)
#pragma unroll
            for (int i = 0; i < 4; ++i) { accG[t][nt][i] = 0.f; accM[t][nt][i] = 0.f; }

    for (int kt = 0; kt < 128; ++kt) {
        CP_WAIT5();
        __syncthreads();

        const int st = kt % NS;
        const uint32_t Ab = sb + SM_STAGES + st * STG_BYTES;
        const uint32_t Bb = Ab + 8192;

#pragma unroll
        for (int ks = 0; ks < 2; ++ks) {
            uint32_t af[2][4], bfr[4][4];
#pragma unroll
            for (int t = 0; t < 2; ++t) {
                uint32_t co = ((uint32_t)(ks * 2 + chh) ^ axr[t]) * 16;
                ldsm4(af[t], Ab + aoff[t] + co);
            }
#pragma unroll
            for (int bb = 0; bb < 4; ++bb)
                ldsm4t(bfr[bb], Bb + boff[ks] + bcol[bb]);
#pragma unroll
            for (int t = 0; t < 2; ++t)
#pragma unroll
                for (int nt = 0; nt < 8; ++nt)
                    mma_f16(accG[t][nt], af[t], &bfr[nt >> 1][(nt & 1) * 2]);
        }

        if ((kt & 3) == 3) {   // end of 128-K group: fold with scales
            const int g = kt >> 2;
            const float* sg = s_sc + g * 128 + wn * 64 + (lane & 3) * 2;
#pragma unroll
            for (int nt = 0; nt < 8; ++nt) {
                float2 sv = *(const float2*)(sg + nt * 8);
#pragma unroll
                for (int t = 0; t < 2; ++t) {
                    accM[t][nt][0] += sv.x * accG[t][nt][0];
                    accM[t][nt][1] += sv.y * accG[t][nt][1];
                    accM[t][nt][2] += sv.x * accG[t][nt][2];
                    accM[t][nt][3] += sv.y * accG[t][nt][3];
                    accG[t][nt][0] = 0.f; accG[t][nt][1] = 0.f;
                    accG[t][nt][2] = 0.f; accG[t][nt][3] = 0.f;
                }
            }
        }

        __syncthreads();
        if (kt + NS < 128) load_stage(kt + NS, st);
        CP_COMMIT();
    }

    // epilogue
#pragma unroll
    for (int t = 0; t < 2; ++t) {
        int row0 = m0 + wm * 32 + t * 16 + (lane >> 2);
#pragma unroll
        for (int nt = 0; nt < 8; ++nt) {
            int col = n0 + wn * 64 + nt * 8 + (lane & 3) * 2;
            float2 b = *(const float2*)(bias + col);
            float2 o0, o1;
            o0.x = accM[t][nt][0] + b.x;  o0.y = accM[t][nt][1] + b.y;
            o1.x = accM[t][nt][2] + b.x;  o1.y = accM[t][nt][3] + b.y;
            *(float2*)(C + (size_t)row0 * NNV + col)       = o0;
            *(float2*)(C + (size_t)(row0 + 8) * NNV + col) = o1;
        }
    }
}

// ---------------------------------------------------------------------------
// Host. Inputs: x, scales, zero_points, bias, qweight
// ---------------------------------------------------------------------------
extern "C" void kernel_launch(void* const* d_in, const int* in_sizes, int n_in,
                              void* d_out, int out_size)
{
    const float* x      = (const float*)d_in[0];
    const float* scales = (const float*)d_in[1];
    const float* zp     = (const float*)d_in[2];
    const float* bias   = (const float*)d_in[3];
    const int*   qw     = (const int*)d_in[4];
    float*       out    = (float*)d_out;

    split_x_kernel<<<(MMV * KKV / 4) / 256, 256>>>((const float4*)x);
    dequant_w_kernel<<<(KKV / 8) * NNV / 256, 256>>>(qw, zp);

    static bool attr_set = false;
    if (!attr_set) {
        cudaFuncSetAttribute(gemm_kernel, cudaFuncAttributeMaxDynamicSharedMemorySize, SMEM_TOTAL);
        attr_set = true;
    }
    gemm_kernel<<<dim3(NNV / 128, MMV / 128), 256, SMEM_TOTAL>>>(scales, bias, out);
}

// round 6
// speedup vs baseline: 1.9866x; 1.3115x over previous
#include <cuda_runtime.h>
#include <cuda_fp16.h>
#include <cstdint>

#define MMV 2048
#define NNV 4096
#define KKV 4096

// Scratch (__device__ globals; no allocations allowed)
__device__ __align__(16) __half g_xh[(size_t)MMV * KKV];  // fp16(x)
__device__ __align__(16) __half g_wi[(size_t)KKV * NNV];  // (q - z) exact integer, [K][N]

// ---------------------------------------------------------------------------
// asm helpers
// ---------------------------------------------------------------------------
__device__ __forceinline__ void ldsm4(uint32_t* r, uint32_t addr) {
    asm volatile("ldmatrix.sync.aligned.m8n8.x4.shared.b16 {%0,%1,%2,%3}, [%4];"
                 : "=r"(r[0]), "=r"(r[1]), "=r"(r[2]), "=r"(r[3]) : "r"(addr));
}
__device__ __forceinline__ void ldsm4t(uint32_t* r, uint32_t addr) {
    asm volatile("ldmatrix.sync.aligned.m8n8.x4.trans.shared.b16 {%0,%1,%2,%3}, [%4];"
                 : "=r"(r[0]), "=r"(r[1]), "=r"(r[2]), "=r"(r[3]) : "r"(addr));
}
__device__ __forceinline__ void mma_f16(float* c, const uint32_t* a, const uint32_t* b) {
    asm volatile("mma.sync.aligned.m16n8k16.row.col.f32.f16.f16.f32 "
                 "{%0,%1,%2,%3}, {%4,%5,%6,%7}, {%8,%9}, {%0,%1,%2,%3};"
                 : "+f"(c[0]), "+f"(c[1]), "+f"(c[2]), "+f"(c[3])
                 : "r"(a[0]), "r"(a[1]), "r"(a[2]), "r"(a[3]), "r"(b[0]), "r"(b[1]));
}
__device__ __forceinline__ void cpa16(uint32_t s, const void* g) {
    asm volatile("cp.async.cg.shared.global [%0], [%1], 16;" :: "r"(s), "l"(g));
}
#define CP_COMMIT() asm volatile("cp.async.commit_group;" ::: "memory")
#define CP_WAIT2()  asm volatile("cp.async.wait_group 2;" ::: "memory")

// ---------------------------------------------------------------------------
// Prep 1: x -> fp16
// ---------------------------------------------------------------------------
__global__ void split_x_kernel(const float4* __restrict__ x4) {
    size_t i = (size_t)blockIdx.x * blockDim.x + threadIdx.x;
    float4 v = x4[i];
    __align__(8) __half h[4];
    h[0] = __float2half_rn(v.x); h[1] = __float2half_rn(v.y);
    h[2] = __float2half_rn(v.z); h[3] = __float2half_rn(v.w);
    ((uint2*)g_xh)[i] = *(uint2*)h;
}

// ---------------------------------------------------------------------------
// Prep 2: Wint[k][n] = q - clip(round(zp),0,15)   (exact small integer, fp16)
// ---------------------------------------------------------------------------
__global__ void dequant_w_kernel(const int* __restrict__ qw,
                                 const float* __restrict__ zp) {
    int T = blockIdx.x * blockDim.x + threadIdx.x;
    int n  = T & (NNV - 1);
    int kp = T >> 12;
    int g  = kp >> 4;
    float z = fminf(fmaxf(rintf(zp[g * NNV + n]), 0.0f), 15.0f);
    int q = qw[(size_t)kp * NNV + n];
#pragma unroll
    for (int j = 0; j < 8; ++j) {
        int w = (q >> (4 * j)) & 15;
        g_wi[(size_t)(kp * 8 + j) * NNV + n] = __float2half_rn((float)w - z);
    }
}

// ---------------------------------------------------------------------------
// GEMM: C = xh @ Wint with per-group fp32 scale fold, + bias
// CTA tile 128x128, BK=64, 8 warps (4m x 2n), warp tile 32x64
// smem: [0,16K) scales; NS=4 stages x (A 16K | B 16K)
// ---------------------------------------------------------------------------
#define NS 4
#define STG_BYTES 32768
#define SM_STAGES 16384
#define SMEM_TOTAL (SM_STAGES + NS * STG_BYTES)   // 147456

__global__ void __launch_bounds__(256, 1)
gemm_kernel(const float* __restrict__ scales,
            const float* __restrict__ bias,
            float* __restrict__ C)
{
    extern __shared__ __align__(16) char smem[];
    const uint32_t sb = (uint32_t)__cvta_generic_to_shared(smem);
    const int tid = threadIdx.x, lane = tid & 31, wid = tid >> 5;
    const int wm = wid & 3, wn = wid >> 2;
    const int m0 = blockIdx.y * 128, n0 = blockIdx.x * 128;

    // stage clipped scales [32 groups][128 cols]
    float* s_sc = (float*)smem;
    for (int i = tid; i < 4096; i += 256) {
        int g = i >> 7, j = i & 127;
        float s = scales[g * NNV + n0 + j];
        s_sc[i] = fminf(fmaxf(s, 1e-5f), 1e4f);
    }

    // loader: A 128x64 fp16 (1024 x 16B chunks), B 64x128 fp16 (1024 chunks)
    auto load_stage = [&](int kt, int st) {
        uint32_t base = sb + SM_STAGES + st * STG_BYTES;
#pragma unroll
        for (int j = 0; j < 4; ++j) {
            int q = tid + j * 256;
            int r = q >> 3, c = q & 7;
            uint32_t so = base + (uint32_t)(r * 8 + (c ^ (r & 7))) * 16;
            cpa16(so, g_xh + (size_t)(m0 + r) * KKV + kt * 64 + c * 8);
        }
#pragma unroll
        for (int j = 0; j < 4; ++j) {
            int q = tid + j * 256;
            int r = q >> 4, c = q & 15;
            uint32_t so = base + 16384 + (uint32_t)(r * 16 + (c ^ (r & 7))) * 16;
            cpa16(so, g_wi + (size_t)(kt * 64 + r) * NNV + n0 + c * 8);
        }
    };

    // prefill NS-1 = 3 stages
#pragma unroll
    for (int s = 0; s < NS - 1; ++s) { load_stage(s, s); CP_COMMIT(); }

    // ldmatrix address precompute
    const int lane_r = lane & 15, chh = lane >> 4;
    uint32_t arow[2], axr[2];
#pragma unroll
    for (int t = 0; t < 2; ++t) {
        int r = wm * 32 + t * 16 + lane_r;
        arow[t] = (uint32_t)r * 128;            // 128 B per A row
        axr[t]  = (uint32_t)(r & 7);
    }
    const uint32_t xb = (uint32_t)(lane_r & 7);
    uint32_t bcol[4];
#pragma unroll
    for (int bb = 0; bb < 4; ++bb)
        bcol[bb] = (uint32_t)(wn * 8 + (((uint32_t)(bb * 2 + chh)) ^ xb)) * 16;
    uint32_t boff[4];
#pragma unroll
    for (int ks = 0; ks < 4; ++ks)
        boff[ks] = (uint32_t)(ks * 16 + lane_r) * 256;   // 256 B per B row

    float accG[2][8][4];
    float accM[2][8][4];
#pragma unroll
    for (int t = 0; t < 2; ++t)
#pragma unroll
        for (int nt = 0; nt < 8; ++nt)
#pragma unroll
            for (int i = 0; i < 4; ++i) { accG[t][nt][i] = 0.f; accM[t][nt][i] = 0.f; }

    for (int kt = 0; kt < 64; ++kt) {
        CP_WAIT2();
        __syncthreads();

        const int st = kt & 3;
        const uint32_t Ab = sb + SM_STAGES + st * STG_BYTES;
        const uint32_t Bb = Ab + 16384;

        // issue next loads into the slot freed last iteration
        if (kt + NS - 1 < 64) load_stage(kt + NS - 1, (kt + NS - 1) & 3);
        CP_COMMIT();

#pragma unroll
        for (int ks = 0; ks < 4; ++ks) {
            uint32_t af[2][4], bfr[4][4];
#pragma unroll
            for (int t = 0; t < 2; ++t) {
                uint32_t co = ((uint32_t)(ks * 2 + chh) ^ axr[t]) * 16;
                ldsm4(af[t], Ab + arow[t] + co);
            }
#pragma unroll
            for (int bb = 0; bb < 4; ++bb)
                ldsm4t(bfr[bb], Bb + boff[ks] + bcol[bb]);
#pragma unroll
            for (int t = 0; t < 2; ++t)
#pragma unroll
                for (int nt = 0; nt < 8; ++nt)
                    mma_f16(accG[t][nt], af[t], &bfr[nt >> 1][(nt & 1) * 2]);
        }

        if (kt & 1) {   // end of 128-K group: fold with scales
            const int g = kt >> 1;
            const float* sg = s_sc + g * 128 + wn * 64 + (lane & 3) * 2;
#pragma unroll
            for (int nt = 0; nt < 8; ++nt) {
                float2 sv = *(const float2*)(sg + nt * 8);
#pragma unroll
                for (int t = 0; t < 2; ++t) {
                    accM[t][nt][0] += sv.x * accG[t][nt][0];
                    accM[t][nt][1] += sv.y * accG[t][nt][1];
                    accM[t][nt][2] += sv.x * accG[t][nt][2];
                    accM[t][nt][3] += sv.y * accG[t][nt][3];
                    accG[t][nt][0] = 0.f; accG[t][nt][1] = 0.f;
                    accG[t][nt][2] = 0.f; accG[t][nt][3] = 0.f;
                }
            }
        }
    }

    // epilogue
#pragma unroll
    for (int t = 0; t < 2; ++t) {
        int row0 = m0 + wm * 32 + t * 16 + (lane >> 2);
#pragma unroll
        for (int nt = 0; nt < 8; ++nt) {
            int col = n0 + wn * 64 + nt * 8 + (lane & 3) * 2;
            float2 b = *(const float2*)(bias + col);
            float2 o0, o1;
            o0.x = accM[t][nt][0] + b.x;  o0.y = accM[t][nt][1] + b.y;
            o1.x = accM[t][nt][2] + b.x;  o1.y = accM[t][nt][3] + b.y;
            *(float2*)(C + (size_t)row0 * NNV + col)       = o0;
            *(float2*)(C + (size_t)(row0 + 8) * NNV + col) = o1;
        }
    }
}

// ---------------------------------------------------------------------------
// Host. Inputs: x, scales, zero_points, bias, qweight
// ---------------------------------------------------------------------------
extern "C" void kernel_launch(void* const* d_in, const int* in_sizes, int n_in,
                              void* d_out, int out_size)
{
    const float* x      = (const float*)d_in[0];
    const float* scales = (const float*)d_in[1];
    const float* zp     = (const float*)d_in[2];
    const float* bias   = (const float*)d_in[3];
    const int*   qw     = (const int*)d_in[4];
    float*       out    = (float*)d_out;

    split_x_kernel<<<(MMV * KKV / 4) / 256, 256>>>((const float4*)x);
    dequant_w_kernel<<<(KKV / 8) * NNV / 256, 256>>>(qw, zp);

    static bool attr_set = false;
    if (!attr_set) {
        cudaFuncSetAttribute(gemm_kernel, cudaFuncAttributeMaxDynamicSharedMemorySize, SMEM_TOTAL);
        attr_set = true;
    }
    gemm_kernel<<<dim3(NNV / 128, MMV / 128), 256, SMEM_TOTAL>>>(scales, bias, out);
}